// round 2
// baseline (speedup 1.0000x reference)
#include <cuda_runtime.h>
#include <cuda_bf16.h>

// Problem constants
#define NBATCH 4
#define NSEQ   2048
#define NDIMS  1024
#define NHEADS 16
#define HD     64         // head dim
#define NROT   32         // HD/2
#define NROWS  (NBATCH*NSEQ*NHEADS)   // 131072

// Scratch (allocation-free rule: __device__ globals)
__device__ __align__(16) float g_M[HD * HD];  // combined Givens-chain @ r_matrix

// ---------------------------------------------------------------------------
// Setup kernel: build M = T0 * T1 * ... * T31 * R (row @ M == scan+matmul).
// Thread t owns COLUMN t of the accumulator; every read and write touches only
// Ms[. * 64 + t], so there are NO cross-thread dependencies -> no syncs at all.
// Left-multiplying by T_k (applied in reverse k order, starting from R):
//   row_i' = c*row_i - s*row_j ; row_j' = s*row_i + c*row_j   (i != j)
//   row_i' = s*row_i                                          (i == j)
// ---------------------------------------------------------------------------
__global__ void build_M_kernel(const float* __restrict__ thetas,
                               const float* __restrict__ tscale,
                               const float* __restrict__ R,
                               const int*   __restrict__ pairs) {
    __shared__ float Ms[HD * HD];
    const int t = threadIdx.x;  // 0..63, owns column t
#pragma unroll 4
    for (int d = 0; d < HD; d++) Ms[d * HD + t] = R[d * HD + t];
    const float ts = tscale[0];
    for (int k = NROT - 1; k >= 0; k--) {
        const int i = pairs[2 * k];
        const int j = pairs[2 * k + 1];
        const float th = thetas[k] * ts;
        const float c = cosf(th);
        const float s = sinf(th);
        const float a = Ms[i * HD + t];
        const float b = Ms[j * HD + t];
        if (i == j) {
            Ms[i * HD + t] = s * a;
        } else {
            Ms[i * HD + t] = c * a - s * b;
            Ms[j * HD + t] = s * a + c * b;
        }
    }
#pragma unroll 4
    for (int d = 0; d < HD; d++) g_M[d * HD + t] = Ms[d * HD + t];
}

// ---------------------------------------------------------------------------
// Packed f32x2 FMA (Blackwell sm_100+): two fp32 FMAs per instruction
// ---------------------------------------------------------------------------
__device__ __forceinline__ unsigned long long fma_f32x2(unsigned long long a,
                                                        unsigned long long b,
                                                        unsigned long long c) {
    unsigned long long d;
    asm("fma.rn.f32x2 %0, %1, %2, %3;" : "=l"(d) : "l"(a), "l"(b), "l"(c));
    return d;
}

// ---------------------------------------------------------------------------
// Main kernel: TWO rows (head-vectors of 64 floats) per thread, sharing every
// M load -> LDS.128 : FFMA2 ratio improves 1:2 -> 1:4.
// Block = 128 threads = 256 consecutive rows = 16 consecutive positions.
// Trig table for the block's 16 positions is computed in-kernel (512 sincosf
// spread over 128 threads), removing the separate trig kernel.
// ---------------------------------------------------------------------------
__global__ void __launch_bounds__(128, 3)
rotary_main_kernel(const float* __restrict__ x,
                   const float* __restrict__ inv_freq,
                   float* __restrict__ out) {
    __shared__ __align__(16) float MS[HD * HD];   // 16 KB
    __shared__ float SS[16][NROT];
    __shared__ float CS[16][NROT];

    const int t = threadIdx.x;
    const long long base = (long long)blockIdx.x * (256LL * HD);

    // Load M into shared (float4 coalesced)
    for (int i = t; i < (HD * HD) / 4; i += 128)
        ((float4*)MS)[i] = ((const float4*)g_M)[i];

    // Compute this block's 16 positions worth of sin/cos (4 sincosf per thread)
    {
        const int s0 = (blockIdx.x * 16) & (NSEQ - 1);
#pragma unroll
        for (int i = t; i < 16 * NROT; i += 128) {
            const int ls = i >> 5, n = i & 31;
            const float ang = (float)(s0 + ls) * inv_freq[n];
            float sv, cv;
            sincosf(ang, &sv, &cv);
            SS[ls][n] = sv;
            CS[ls][n] = cv;
        }
    }
    __syncthreads();

    // Packed accumulators for 2 rows: accR[p] = (w[2p], w[2p+1])
    unsigned long long acc0[NROT], acc1[NROT];
#pragma unroll
    for (int p = 0; p < NROT; p++) { acc0[p] = 0ull; acc1[p] = 0ull; }

    const float4* xrow0 = (const float4*)(x + base) + t * 16;          // row t
    const float4* xrow1 = (const float4*)(x + base) + (t + 128) * 16;  // row t+128
    const ulonglong2* Mp = (const ulonglong2*)MS;  // 16 ulonglong2 per M-row

#pragma unroll 2
    for (int i = 0; i < 16; i++) {
        const float4 v0 = xrow0[i];
        const float4 v1 = xrow1[i];
#pragma unroll
        for (int dd = 0; dd < 4; dd++) {
            const float a0 = (dd == 0) ? v0.x : (dd == 1) ? v0.y : (dd == 2) ? v0.z : v0.w;
            const float a1 = (dd == 0) ? v1.x : (dd == 1) ? v1.y : (dd == 2) ? v1.z : v1.w;
            unsigned long long vv0, vv1;
            asm("mov.b64 %0, {%1, %1};" : "=l"(vv0) : "f"(a0));
            asm("mov.b64 %0, {%1, %1};" : "=l"(vv1) : "f"(a1));
            const ulonglong2* mrow = Mp + (i * 4 + dd) * 16;
#pragma unroll
            for (int q = 0; q < 16; q++) {
                const ulonglong2 m = mrow[q];   // uniform address -> smem broadcast
                acc0[2 * q]     = fma_f32x2(vv0, m.x, acc0[2 * q]);
                acc0[2 * q + 1] = fma_f32x2(vv0, m.y, acc0[2 * q + 1]);
                acc1[2 * q]     = fma_f32x2(vv1, m.x, acc1[2 * q]);
                acc1[2 * q + 1] = fma_f32x2(vv1, m.y, acc1[2 * q + 1]);
            }
        }
    }

    // RoPE epilogue + scale by sqrt(1024)=32.
    //   out[p]    = (w[2p]*cos_p - w[2p+1]*sin_p) * 32
    //   out[p+32] = (w[2p]*sin_p + w[2p+1]*cos_p) * 32
    const int ls0 = t >> 4;        // position slot of row t (16 heads/position)
    const int ls1 = (t >> 4) + 8;  // position slot of row t+128
    float4* orow0 = (float4*)(out + base) + t * 16;
    float4* orow1 = (float4*)(out + base) + (t + 128) * 16;
#pragma unroll
    for (int q = 0; q < 8; q++) {
        float lo0[4], hi0[4], lo1[4], hi1[4];
#pragma unroll
        for (int u = 0; u < 4; u++) {
            const int p = 4 * q + u;
            float a, b;
            asm("mov.b64 {%0, %1}, %2;" : "=f"(a), "=f"(b) : "l"(acc0[p]));
            const float c0 = CS[ls0][p], s0 = SS[ls0][p];
            lo0[u] = (a * c0 - b * s0) * 32.0f;
            hi0[u] = (a * s0 + b * c0) * 32.0f;
            asm("mov.b64 {%0, %1}, %2;" : "=f"(a), "=f"(b) : "l"(acc1[p]));
            const float c1 = CS[ls1][p], s1 = SS[ls1][p];
            lo1[u] = (a * c1 - b * s1) * 32.0f;
            hi1[u] = (a * s1 + b * c1) * 32.0f;
        }
        orow0[q]     = make_float4(lo0[0], lo0[1], lo0[2], lo0[3]);
        orow0[q + 8] = make_float4(hi0[0], hi0[1], hi0[2], hi0[3]);
        orow1[q]     = make_float4(lo1[0], lo1[1], lo1[2], lo1[3]);
        orow1[q + 8] = make_float4(hi1[0], hi1[1], hi1[2], hi1[3]);
    }
}

// ---------------------------------------------------------------------------
// kernel_launch: inputs in metadata order:
//   0: x (f32, 8388608)  1: thetas (f32,32)  2: theta_scale (f32,1)
//   3: r_matrix (f32,4096)  4: inv_freq (f32,32)  5: pairs (i32,64)
// ---------------------------------------------------------------------------
extern "C" void kernel_launch(void* const* d_in, const int* in_sizes, int n_in,
                              void* d_out, int out_size) {
    const float* x        = (const float*)d_in[0];
    const float* thetas   = (const float*)d_in[1];
    const float* tscale   = (const float*)d_in[2];
    const float* R        = (const float*)d_in[3];
    const float* inv_freq = (const float*)d_in[4];
    const int*   pairs    = (const int*)d_in[5];
    float* out = (float*)d_out;

    build_M_kernel<<<1, 64>>>(thetas, tscale, R, pairs);
    rotary_main_kernel<<<NROWS / 256, 128>>>(x, inv_freq, out);
}

// round 4
// speedup vs baseline: 2.1078x; 2.1078x over previous
#include <cuda_runtime.h>
#include <cuda_bf16.h>
#include <cstdint>

// Problem constants
#define NBATCH 4
#define NSEQ   2048
#define NDIMS  1024
#define NHEADS 16
#define HD     64
#define NROT   32
#define NROWS  (NBATCH*NSEQ*NHEADS)   // 131072
#define ROWS_PER_CTA 64
#define NCTAS  (NROWS / ROWS_PER_CTA) // 2048

#define STRIDE_AB 72   // bf16 elements per padded row (conflict-free frag loads)
#define STRIDE_ST 68   // floats per padded staging row (68*4=272 = 17*16, f4-aligned)

// Device scratch (allocation-free rule)
__device__ __align__(16) float g_M[HD * HD];
__device__ __align__(16) __nv_bfloat16 g_B[2][HD * STRIDE_AB];  // [hi/lo][n*72+k]

// ---------------------------------------------------------------------------
// Setup: M = T0*T1*...*T31 * R.  Thread t owns column t -> no syncs needed.
// Also emits B = M^T split into bf16 hi/lo with padded rows for the main GEMM.
// ---------------------------------------------------------------------------
__global__ void build_M_kernel(const float* __restrict__ thetas,
                               const float* __restrict__ tscale,
                               const float* __restrict__ R,
                               const int*   __restrict__ pairs) {
    __shared__ float Ms[HD * HD];
    const int t = threadIdx.x;  // 0..63
#pragma unroll 4
    for (int d = 0; d < HD; d++) Ms[d * HD + t] = R[d * HD + t];
    const float ts = tscale[0];
    for (int k = NROT - 1; k >= 0; k--) {
        const int i = pairs[2 * k];
        const int j = pairs[2 * k + 1];
        const float th = thetas[k] * ts;
        const float c = cosf(th), s = sinf(th);
        const float a = Ms[i * HD + t];
        const float b = Ms[j * HD + t];
        if (i == j) {
            Ms[i * HD + t] = s * a;
        } else {
            Ms[i * HD + t] = c * a - s * b;
            Ms[j * HD + t] = s * a + c * b;
        }
    }
    // thread t owns column t of M == row t of B (B[n][k] = M[k][n])
#pragma unroll 4
    for (int k = 0; k < HD; k++) {
        const float v = Ms[k * HD + t];
        const __nv_bfloat16 hi = __float2bfloat16(v);
        const __nv_bfloat16 lo = __float2bfloat16(v - __bfloat162float(hi));
        g_B[0][t * STRIDE_AB + k] = hi;
        g_B[1][t * STRIDE_AB + k] = lo;
    }
}

// ---------------------------------------------------------------------------
// m16n8k16 bf16 MMA with fp32 accumulate (portable PTX; HMMA in SASS)
// ---------------------------------------------------------------------------
__device__ __forceinline__ void mma16816(float* d,
                                         uint32_t a0, uint32_t a1, uint32_t a2, uint32_t a3,
                                         uint32_t b0, uint32_t b1) {
    asm volatile(
        "mma.sync.aligned.m16n8k16.row.col.f32.bf16.bf16.f32 "
        "{%0,%1,%2,%3}, {%4,%5,%6,%7}, {%8,%9}, {%0,%1,%2,%3};"
        : "+f"(d[0]), "+f"(d[1]), "+f"(d[2]), "+f"(d[3])
        : "r"(a0), "r"(a1), "r"(a2), "r"(a3), "r"(b0), "r"(b1));
}

__device__ __forceinline__ uint32_t pack_bf16x2(float x, float y) {
    __nv_bfloat162 p = {__float2bfloat16(x), __float2bfloat16(y)};
    return *(uint32_t*)&p;
}

// ---------------------------------------------------------------------------
// Main kernel: 64 rows per CTA (4 warps x 16 rows). GEMM via HMMA bf16
// 3-term hi/lo split, RoPE applied in-register on D-fragment column pairs,
// coalesced float4 I/O through padded smem staging.
// ---------------------------------------------------------------------------
__global__ void __launch_bounds__(128)
rotary_mma_kernel(const float* __restrict__ x,
                  const float* __restrict__ inv_freq,
                  float* __restrict__ out) {
    // A tiles (hi+lo) = 2*64*72*2B = 18432B; staging (64*68*4 = 17408B) overlays it
    static __shared__ __align__(16) char bufA[2 * ROWS_PER_CTA * STRIDE_AB * 2];
    static __shared__ __align__(16) __nv_bfloat16 Bsm[2][HD * STRIDE_AB];  // 18432B
    __shared__ float SS[4][NROT], CS[4][NROT];

    const int t    = threadIdx.x;
    const int wid  = t >> 5;
    const int lane = t & 31;
    const int bid  = blockIdx.x;
    const int r    = lane >> 2;   // row-in-quad
    const int c    = lane & 3;    // col-quad

    __nv_bfloat16* Ahi = (__nv_bfloat16*)bufA;
    __nv_bfloat16* Alo = Ahi + ROWS_PER_CTA * STRIDE_AB;

    // ---- Load X tile (64x64 fp32 = 1024 float4), split to bf16 hi/lo in smem ----
    {
        const float4* xg = (const float4*)x + (long long)bid * 1024;
#pragma unroll
        for (int it = 0; it < 8; it++) {
            const int f   = it * 128 + t;
            const int row = f >> 4;
            const int q   = f & 15;
            const float4 v = xg[f];
            const __nv_bfloat16 hx = __float2bfloat16(v.x), hy = __float2bfloat16(v.y);
            const __nv_bfloat16 hz = __float2bfloat16(v.z), hw = __float2bfloat16(v.w);
            uint2 hp, lp;
            {
                __nv_bfloat162 p0 = {hx, hy}, p1 = {hz, hw};
                hp.x = *(uint32_t*)&p0; hp.y = *(uint32_t*)&p1;
            }
            lp.x = pack_bf16x2(v.x - __bfloat162float(hx), v.y - __bfloat162float(hy));
            lp.y = pack_bf16x2(v.z - __bfloat162float(hz), v.w - __bfloat162float(hw));
            *(uint2*)(Ahi + row * STRIDE_AB + q * 4) = hp;
            *(uint2*)(Alo + row * STRIDE_AB + q * 4) = lp;
        }
    }

    // ---- Copy pre-split B (hi+lo, 18432B = 1152 uint4) from global ----
    {
        const uint4* src = (const uint4*)g_B;
        uint4* dst = (uint4*)Bsm;
#pragma unroll
        for (int i = t; i < 1152; i += 128) dst[i] = src[i];
    }

    // ---- Trig: CTA covers 4 positions x 32 freqs = 128 entries (1/thread) ----
    {
        const int ls = t >> 5, n = t & 31;
        const int pos = (bid * 4 + ls) & (NSEQ - 1);
        float sv, cv;
        sincosf((float)pos * inv_freq[n], &sv, &cv);
        SS[ls][n] = sv;
        CS[ls][n] = cv;
    }
    __syncthreads();

    // ---- GEMM: warp owns rows [wid*16, wid*16+16), all 64 cols ----
    float acc[8][4];
#pragma unroll
    for (int n = 0; n < 8; n++)
#pragma unroll
        for (int u = 0; u < 4; u++) acc[n][u] = 0.0f;

    const int arow = wid * 16 + r;
#pragma unroll
    for (int ks = 0; ks < 4; ks++) {
        const int abase = arow * STRIDE_AB + ks * 16 + c * 2;
        const uint32_t ah0 = *(const uint32_t*)(Ahi + abase);
        const uint32_t ah1 = *(const uint32_t*)(Ahi + abase + 8 * STRIDE_AB);
        const uint32_t ah2 = *(const uint32_t*)(Ahi + abase + 8);
        const uint32_t ah3 = *(const uint32_t*)(Ahi + abase + 8 * STRIDE_AB + 8);
        const uint32_t al0 = *(const uint32_t*)(Alo + abase);
        const uint32_t al1 = *(const uint32_t*)(Alo + abase + 8 * STRIDE_AB);
        const uint32_t al2 = *(const uint32_t*)(Alo + abase + 8);
        const uint32_t al3 = *(const uint32_t*)(Alo + abase + 8 * STRIDE_AB + 8);
#pragma unroll
        for (int nt = 0; nt < 8; nt++) {
            const int bbase = (nt * 8 + r) * STRIDE_AB + ks * 16 + c * 2;
            const uint32_t bh0 = *(const uint32_t*)(Bsm[0] + bbase);
            const uint32_t bh1 = *(const uint32_t*)(Bsm[0] + bbase + 8);
            const uint32_t bl0 = *(const uint32_t*)(Bsm[1] + bbase);
            const uint32_t bl1 = *(const uint32_t*)(Bsm[1] + bbase + 8);
            mma16816(acc[nt], ah0, ah1, ah2, ah3, bh0, bh1);
            mma16816(acc[nt], ah0, ah1, ah2, ah3, bl0, bl1);
            mma16816(acc[nt], al0, al1, al2, al3, bh0, bh1);
        }
    }

    __syncthreads();  // A-tile reads done; safe to overlay staging

    // ---- RoPE in registers; stage to padded smem ----
    // D frag: {c0,c1} = row (wid*16+r),  cols (2p, 2p+1); {c2,c3} = row +8.
    // p = nt*4 + c.  out[p] = (w_e*cos - w_o*sin)*32 ; out[p+32] = (w_e*sin + w_o*cos)*32
    {
        float* ST = (float*)bufA;
        const int row0 = wid * 16 + r;
#pragma unroll
        for (int nt = 0; nt < 8; nt++) {
            const int p  = nt * 4 + c;
            const float cs = CS[wid][p];
            const float sn = SS[wid][p];
            ST[row0 * STRIDE_ST + p]            = (acc[nt][0] * cs - acc[nt][1] * sn) * 32.0f;
            ST[row0 * STRIDE_ST + p + 32]       = (acc[nt][0] * sn + acc[nt][1] * cs) * 32.0f;
            ST[(row0 + 8) * STRIDE_ST + p]      = (acc[nt][2] * cs - acc[nt][3] * sn) * 32.0f;
            ST[(row0 + 8) * STRIDE_ST + p + 32] = (acc[nt][2] * sn + acc[nt][3] * cs) * 32.0f;
        }
    }
    __syncthreads();

    // ---- Coalesced float4 store ----
    {
        const float* ST = (const float*)bufA;
        float4* og = (float4*)out + (long long)bid * 1024;
#pragma unroll
        for (int it = 0; it < 8; it++) {
            const int f   = it * 128 + t;
            const int row = f >> 4;
            const int c4  = f & 15;
            og[f] = *(const float4*)(ST + row * STRIDE_ST + c4 * 4);
        }
    }
}

// ---------------------------------------------------------------------------
// kernel_launch: 0:x 1:thetas 2:theta_scale 3:r_matrix 4:inv_freq 5:pairs
// ---------------------------------------------------------------------------
extern "C" void kernel_launch(void* const* d_in, const int* in_sizes, int n_in,
                              void* d_out, int out_size) {
    const float* x        = (const float*)d_in[0];
    const float* thetas   = (const float*)d_in[1];
    const float* tscale   = (const float*)d_in[2];
    const float* R        = (const float*)d_in[3];
    const float* inv_freq = (const float*)d_in[4];
    const int*   pairs    = (const int*)d_in[5];
    float* out = (float*)d_out;

    build_M_kernel<<<1, 64>>>(thetas, tscale, R, pairs);
    rotary_mma_kernel<<<NCTAS, 128>>>(x, inv_freq, out);
}

// round 5
// speedup vs baseline: 2.4149x; 1.1457x over previous
#include <cuda_runtime.h>
#include <cuda_bf16.h>
#include <cstdint>

// Problem constants
#define NBATCH 4
#define NSEQ   2048
#define NDIMS  1024
#define NHEADS 16
#define HD     64
#define NROT   32
#define NROWS  (NBATCH*NSEQ*NHEADS)    // 131072
#define ROWS_PER_CTA 128
#define NTHREADS 256
#define NCTAS  (NROWS / ROWS_PER_CTA)  // 1024

#define STRIDE_AB 72   // bf16 per padded row: 144B (16B-aligned), conflict-free frags
#define STRIDE_ST 68   // floats per padded staging row: 272B (16B-aligned)

// ---------------------------------------------------------------------------
// SMEM layout (dynamic, 73984 B). Staging (128*68*4 = 34816B) overlays A tiles.
// ---------------------------------------------------------------------------
#define SM_AHI   0                        // 128*72*2 = 18432
#define SM_ALO   18432                    // 18432
#define SM_BHI   36864                    // 64*72*2 = 9216
#define SM_BLO   46080                    // 9216
#define SM_MS    55296                    // 64*64*4 = 16384
#define SM_SS    71680                    // 8*32*4 = 1024
#define SM_CS    72704                    // 1024
#define SM_CTAB  73728                    // 32*4 chain cos
#define SM_STAB  73856                    // 32*4 chain sin
#define SM_PR    73984                    // 64*4 pairs
#define SMEM_BYTES 74240
#define SM_STAGE 0

// ---------------------------------------------------------------------------
// m16n8k16 bf16 MMA, fp32 accumulate (portable PTX -> HMMA)
// ---------------------------------------------------------------------------
__device__ __forceinline__ void mma16816(float* d,
                                         uint32_t a0, uint32_t a1, uint32_t a2, uint32_t a3,
                                         uint32_t b0, uint32_t b1) {
    asm volatile(
        "mma.sync.aligned.m16n8k16.row.col.f32.bf16.bf16.f32 "
        "{%0,%1,%2,%3}, {%4,%5,%6,%7}, {%8,%9}, {%0,%1,%2,%3};"
        : "+f"(d[0]), "+f"(d[1]), "+f"(d[2]), "+f"(d[3])
        : "r"(a0), "r"(a1), "r"(a2), "r"(a3), "r"(b0), "r"(b1));
}

__device__ __forceinline__ uint32_t pack_bf16x2(float x, float y) {
    __nv_bfloat162 p = {__float2bfloat16(x), __float2bfloat16(y)};
    return *(uint32_t*)&p;
}

// ---------------------------------------------------------------------------
// Fully fused kernel.
//  Per CTA (128 rows x 64 cols):
//   1. LDG x tile (regs, DRAM latency in flight)
//   2. store A hi/lo bf16 split to smem; compute epilogue trig entry
//   3. warps 0-1: rebuild M = Givens-chain @ R in smem (latency overlapped)
//   4. all: split M^T -> B hi/lo bf16 in smem
//   5. HMMA GEMM (3-term hi/lo split, fp32-accurate)
//   6. RoPE in registers on D-fragment column pairs
//   7. staged, fully-coalesced float4 store
// ---------------------------------------------------------------------------
__global__ void __launch_bounds__(NTHREADS, 3)
rotary_fused_kernel(const float* __restrict__ x,
                    const float* __restrict__ thetas,
                    const float* __restrict__ tscale,
                    const float* __restrict__ R,
                    const float* __restrict__ inv_freq,
                    const int*   __restrict__ pairs,
                    float* __restrict__ out) {
    extern __shared__ __align__(16) char sm[];
    __nv_bfloat16* Ahi = (__nv_bfloat16*)(sm + SM_AHI);
    __nv_bfloat16* Alo = (__nv_bfloat16*)(sm + SM_ALO);
    __nv_bfloat16* Bhi = (__nv_bfloat16*)(sm + SM_BHI);
    __nv_bfloat16* Blo = (__nv_bfloat16*)(sm + SM_BLO);
    float* Ms   = (float*)(sm + SM_MS);
    float* SS   = (float*)(sm + SM_SS);
    float* CS   = (float*)(sm + SM_CS);
    float* CTAB = (float*)(sm + SM_CTAB);
    float* STAB = (float*)(sm + SM_STAB);
    int*   PR   = (int*)  (sm + SM_PR);

    const int t    = threadIdx.x;
    const int wid  = t >> 5;
    const int lane = t & 31;
    const int bid  = blockIdx.x;
    const int r    = lane >> 2;
    const int c    = lane & 3;

    // ---- 1. Issue x-tile loads first (8 float4/thread, MLP=8) ----
    float4 xv[8];
    {
        const float4* xg = (const float4*)x + (long long)bid * 2048;
#pragma unroll
        for (int it = 0; it < 8; it++) xv[it] = xg[it * NTHREADS + t];
    }

    // ---- Small-parameter staging for the chain ----
    if (t < 64) PR[t] = pairs[t];
    if (t < 32) {
        const float th = thetas[t] * tscale[0];
        float sv, cv;
        sincosf(th, &sv, &cv);
        CTAB[t] = cv;
        STAB[t] = sv;
    }
    // R -> Ms (coalesced float4, 4 per thread)
    {
        const float4* Rg = (const float4*)R;
        float4* Mg = (float4*)Ms;
#pragma unroll
        for (int i = 0; i < 4; i++) Mg[i * NTHREADS + t] = Rg[i * NTHREADS + t];
    }

    // ---- 2a. Epilogue trig: 8 positions x 32 freqs, one entry per thread ----
    {
        const int ls = t >> 5, n = t & 31;
        const int pos = (bid * 8 + ls) & (NSEQ - 1);
        float sv, cv;
        sincosf((float)pos * inv_freq[n], &sv, &cv);
        SS[ls * 32 + n] = sv;
        CS[ls * 32 + n] = cv;
    }

    // ---- 2b. A tile: bf16 hi/lo split into padded smem ----
#pragma unroll
    for (int it = 0; it < 8; it++) {
        const int f   = it * NTHREADS + t;
        const int row = f >> 4;
        const int q   = f & 15;
        const float4 v = xv[it];
        const __nv_bfloat16 hx = __float2bfloat16(v.x), hy = __float2bfloat16(v.y);
        const __nv_bfloat16 hz = __float2bfloat16(v.z), hw = __float2bfloat16(v.w);
        uint2 hp, lp;
        {
            __nv_bfloat162 p0 = {hx, hy}, p1 = {hz, hw};
            hp.x = *(uint32_t*)&p0; hp.y = *(uint32_t*)&p1;
        }
        lp.x = pack_bf16x2(v.x - __bfloat162float(hx), v.y - __bfloat162float(hy));
        lp.y = pack_bf16x2(v.z - __bfloat162float(hz), v.w - __bfloat162float(hw));
        *(uint2*)(Ahi + row * STRIDE_AB + q * 4) = hp;
        *(uint2*)(Alo + row * STRIDE_AB + q * 4) = lp;
    }

    __syncthreads();  // Ms, PR, CTAB/STAB ready

    // ---- 3. Givens chain: thread t<64 owns column t of Ms (no cross-thread dep) ----
    if (t < 64) {
        for (int k = NROT - 1; k >= 0; k--) {
            const int i = PR[2 * k];
            const int j = PR[2 * k + 1];
            const float cv = CTAB[k], sv = STAB[k];
            const float a = Ms[i * HD + t];
            const float b = Ms[j * HD + t];
            if (i == j) {
                Ms[i * HD + t] = sv * a;
            } else {
                Ms[i * HD + t] = cv * a - sv * b;
                Ms[j * HD + t] = sv * a + cv * b;
            }
        }
    }
    __syncthreads();  // Ms final

    // ---- 4. B split: B[n][k] = Ms[k][n]; 256 threads, 16 k's each ----
    {
        const int n = t & 63;
        const int part = t >> 6;           // 0..3
        const int k0 = part * 16;
        uint32_t hiw[8], low[8];
#pragma unroll
        for (int u = 0; u < 8; u++) {
            const float v0 = Ms[(k0 + 2 * u) * HD + n];
            const float v1 = Ms[(k0 + 2 * u + 1) * HD + n];
            const __nv_bfloat16 h0 = __float2bfloat16(v0);
            const __nv_bfloat16 h1 = __float2bfloat16(v1);
            __nv_bfloat162 hp = {h0, h1};
            hiw[u] = *(uint32_t*)&hp;
            low[u] = pack_bf16x2(v0 - __bfloat162float(h0), v1 - __bfloat162float(h1));
        }
        uint4* bh = (uint4*)(Bhi + n * STRIDE_AB + k0);
        uint4* bl = (uint4*)(Blo + n * STRIDE_AB + k0);
        bh[0] = make_uint4(hiw[0], hiw[1], hiw[2], hiw[3]);
        bh[1] = make_uint4(hiw[4], hiw[5], hiw[6], hiw[7]);
        bl[0] = make_uint4(low[0], low[1], low[2], low[3]);
        bl[1] = make_uint4(low[4], low[5], low[6], low[7]);
    }
    __syncthreads();  // A + B staged

    // ---- 5. GEMM: warp owns rows [wid*16, wid*16+16), all 64 cols ----
    float acc[8][4];
#pragma unroll
    for (int n = 0; n < 8; n++)
#pragma unroll
        for (int u = 0; u < 4; u++) acc[n][u] = 0.0f;

    const int arow = wid * 16 + r;
#pragma unroll
    for (int ks = 0; ks < 4; ks++) {
        const int abase = arow * STRIDE_AB + ks * 16 + c * 2;
        const uint32_t ah0 = *(const uint32_t*)(Ahi + abase);
        const uint32_t ah1 = *(const uint32_t*)(Ahi + abase + 8 * STRIDE_AB);
        const uint32_t ah2 = *(const uint32_t*)(Ahi + abase + 8);
        const uint32_t ah3 = *(const uint32_t*)(Ahi + abase + 8 * STRIDE_AB + 8);
        const uint32_t al0 = *(const uint32_t*)(Alo + abase);
        const uint32_t al1 = *(const uint32_t*)(Alo + abase + 8 * STRIDE_AB);
        const uint32_t al2 = *(const uint32_t*)(Alo + abase + 8);
        const uint32_t al3 = *(const uint32_t*)(Alo + abase + 8 * STRIDE_AB + 8);
#pragma unroll
        for (int nt = 0; nt < 8; nt++) {
            const int bbase = (nt * 8 + r) * STRIDE_AB + ks * 16 + c * 2;
            const uint32_t bh0 = *(const uint32_t*)(Bhi + bbase);
            const uint32_t bh1 = *(const uint32_t*)(Bhi + bbase + 8);
            const uint32_t bl0 = *(const uint32_t*)(Blo + bbase);
            const uint32_t bl1 = *(const uint32_t*)(Blo + bbase + 8);
            mma16816(acc[nt], ah0, ah1, ah2, ah3, bh0, bh1);
            mma16816(acc[nt], ah0, ah1, ah2, ah3, bl0, bl1);
            mma16816(acc[nt], al0, al1, al2, al3, bh0, bh1);
        }
    }
    __syncthreads();  // A reads done; staging may overlay A

    // ---- 6. RoPE in registers -> padded staging ----
    // D frag: {c0,c1} = row (wid*16+r) cols (2p,2p+1); {c2,c3} = row+8. p = nt*4+c.
    {
        float* ST = (float*)(sm + SM_STAGE);
        const int row0 = wid * 16 + r;
        const float* CSw = CS + wid * 32;
        const float* SSw = SS + wid * 32;
#pragma unroll
        for (int nt = 0; nt < 8; nt++) {
            const int p  = nt * 4 + c;
            const float cs = CSw[p];
            const float sn = SSw[p];
            ST[row0 * STRIDE_ST + p]            = (acc[nt][0] * cs - acc[nt][1] * sn) * 32.0f;
            ST[row0 * STRIDE_ST + p + 32]       = (acc[nt][0] * sn + acc[nt][1] * cs) * 32.0f;
            ST[(row0 + 8) * STRIDE_ST + p]      = (acc[nt][2] * cs - acc[nt][3] * sn) * 32.0f;
            ST[(row0 + 8) * STRIDE_ST + p + 32] = (acc[nt][2] * sn + acc[nt][3] * cs) * 32.0f;
        }
    }
    __syncthreads();

    // ---- 7. Coalesced float4 store ----
    {
        const float* ST = (const float*)(sm + SM_STAGE);
        float4* og = (float4*)out + (long long)bid * 2048;
#pragma unroll
        for (int it = 0; it < 8; it++) {
            const int f   = it * NTHREADS + t;
            const int row = f >> 4;
            const int c4  = f & 15;
            og[f] = *(const float4*)(ST + row * STRIDE_ST + c4 * 4);
        }
    }
}

// ---------------------------------------------------------------------------
// kernel_launch: 0:x 1:thetas 2:theta_scale 3:r_matrix 4:inv_freq 5:pairs
// ---------------------------------------------------------------------------
extern "C" void kernel_launch(void* const* d_in, const int* in_sizes, int n_in,
                              void* d_out, int out_size) {
    const float* x        = (const float*)d_in[0];
    const float* thetas   = (const float*)d_in[1];
    const float* tscale   = (const float*)d_in[2];
    const float* R        = (const float*)d_in[3];
    const float* inv_freq = (const float*)d_in[4];
    const int*   pairs    = (const int*)d_in[5];
    float* out = (float*)d_out;

    static bool attr_set = false;
    if (!attr_set) {
        cudaFuncSetAttribute(rotary_fused_kernel,
                             cudaFuncAttributeMaxDynamicSharedMemorySize, SMEM_BYTES);
        attr_set = true;
    }
    rotary_fused_kernel<<<NCTAS, NTHREADS, SMEM_BYTES>>>(
        x, thetas, tscale, R, inv_freq, pairs, out);
}

// round 6
// speedup vs baseline: 2.4463x; 1.0130x over previous
#include <cuda_runtime.h>
#include <cuda_bf16.h>
#include <cstdint>

// Problem constants
#define NBATCH 4
#define NSEQ   2048
#define NDIMS  1024
#define NHEADS 16
#define HD     64
#define NROT   32
#define NROWS  (NBATCH*NSEQ*NHEADS)   // 131072
#define ROWS_PER_CTA 64
#define NCTAS  (NROWS / ROWS_PER_CTA) // 2048

#define STRIDE_AB 72   // bf16 per padded row (144B): conflict-free LDSM rows
#define STRIDE_ST 68   // floats per padded staging row (272B, 16B aligned)

// Device scratch: pre-split B = M^T in bf16 hi/lo, padded rows
__device__ __align__(16) __nv_bfloat16 g_B[2][HD * STRIDE_AB];

// ---------------------------------------------------------------------------
// Setup: M = T0*...*T31 * R, column t per thread (no syncs; all operands
// pre-staged in smem so the serial chain touches no global memory).
// Emits B[n][k] = M[k][n] split into bf16 hi/lo.
// ---------------------------------------------------------------------------
__global__ void build_M_kernel(const float* __restrict__ thetas,
                               const float* __restrict__ tscale,
                               const float* __restrict__ R,
                               const int*   __restrict__ pairs) {
    __shared__ float Ms[HD * HD];
    __shared__ float CT[NROT], ST[NROT];
    __shared__ int   PR[2 * NROT];
    const int t = threadIdx.x;  // 0..63

    if (t < 2 * NROT) PR[t] = pairs[t];
    if (t < NROT) {
        float sv, cv;
        sincosf(thetas[t] * tscale[0], &sv, &cv);
        CT[t] = cv;
        ST[t] = sv;
    }
#pragma unroll 4
    for (int d = 0; d < HD; d++) Ms[d * HD + t] = R[d * HD + t];
    __syncwarp();
    __syncthreads();

    for (int k = NROT - 1; k >= 0; k--) {
        const int i = PR[2 * k];
        const int j = PR[2 * k + 1];
        const float cv = CT[k], sv = ST[k];
        const float a = Ms[i * HD + t];
        const float b = Ms[j * HD + t];
        if (i == j) {
            Ms[i * HD + t] = sv * a;
        } else {
            Ms[i * HD + t] = cv * a - sv * b;
            Ms[j * HD + t] = sv * a + cv * b;
        }
    }
    // thread t owns column t of M == row t of B
#pragma unroll 4
    for (int k = 0; k < HD; k++) {
        const float v = Ms[k * HD + t];
        const __nv_bfloat16 hi = __float2bfloat16(v);
        const __nv_bfloat16 lo = __float2bfloat16(v - __bfloat162float(hi));
        g_B[0][t * STRIDE_AB + k] = hi;
        g_B[1][t * STRIDE_AB + k] = lo;
    }
}

// ---------------------------------------------------------------------------
// PTX helpers
// ---------------------------------------------------------------------------
__device__ __forceinline__ uint32_t smem_u32(const void* p) {
    uint32_t a;
    asm("{ .reg .u64 t; cvta.to.shared.u64 t, %1; cvt.u32.u64 %0, t; }"
        : "=r"(a) : "l"(p));
    return a;
}
__device__ __forceinline__ void ldsm_x4(uint32_t addr, uint32_t& r0, uint32_t& r1,
                                        uint32_t& r2, uint32_t& r3) {
    asm volatile("ldmatrix.sync.aligned.m8n8.x4.shared.b16 {%0,%1,%2,%3}, [%4];"
                 : "=r"(r0), "=r"(r1), "=r"(r2), "=r"(r3) : "r"(addr));
}
__device__ __forceinline__ void mma16816(float* d,
                                         uint32_t a0, uint32_t a1, uint32_t a2, uint32_t a3,
                                         uint32_t b0, uint32_t b1) {
    asm volatile(
        "mma.sync.aligned.m16n8k16.row.col.f32.bf16.bf16.f32 "
        "{%0,%1,%2,%3}, {%4,%5,%6,%7}, {%8,%9}, {%0,%1,%2,%3};"
        : "+f"(d[0]), "+f"(d[1]), "+f"(d[2]), "+f"(d[3])
        : "r"(a0), "r"(a1), "r"(a2), "r"(a3), "r"(b0), "r"(b1));
}
__device__ __forceinline__ uint32_t pack_bf16x2(float x, float y) {
    __nv_bfloat162 p = {__float2bfloat16(x), __float2bfloat16(y)};
    return *(uint32_t*)&p;
}

// ---------------------------------------------------------------------------
// Main kernel: 64 rows/CTA, 4 warps. HMMA bf16 3-term hi/lo GEMM with all
// fragment traffic through ldmatrix.x4 (conflict-free 144B-stride rows),
// register RoPE, staged coalesced float4 I/O.
// ---------------------------------------------------------------------------
__global__ void __launch_bounds__(128)
rotary_mma_kernel(const float* __restrict__ x,
                  const float* __restrict__ inv_freq,
                  float* __restrict__ out) {
    // A (hi+lo) 18432B; output staging (64*68*4=17408B) overlays it after GEMM
    static __shared__ __align__(16) char bufA[2 * ROWS_PER_CTA * STRIDE_AB * 2];
    static __shared__ __align__(16) __nv_bfloat16 Bsm[2][HD * STRIDE_AB];  // 18432B
    __shared__ float SSm[4][NROT], CSm[4][NROT];

    const int t    = threadIdx.x;
    const int wid  = t >> 5;
    const int lane = t & 31;
    const int bid  = blockIdx.x;
    const int r    = lane >> 2;   // row-in-quad
    const int c    = lane & 3;    // col-quad

    __nv_bfloat16* Ahi = (__nv_bfloat16*)bufA;
    __nv_bfloat16* Alo = Ahi + ROWS_PER_CTA * STRIDE_AB;

    // ---- Load X tile (64x64 fp32 = 1024 float4), bf16 hi/lo split ----
    {
        const float4* xg = (const float4*)x + (long long)bid * 1024;
#pragma unroll
        for (int it = 0; it < 8; it++) {
            const int f   = it * 128 + t;
            const int row = f >> 4;
            const int q   = f & 15;
            const float4 v = xg[f];
            const __nv_bfloat16 hx = __float2bfloat16(v.x), hy = __float2bfloat16(v.y);
            const __nv_bfloat16 hz = __float2bfloat16(v.z), hw = __float2bfloat16(v.w);
            uint2 hp, lp;
            {
                __nv_bfloat162 p0 = {hx, hy}, p1 = {hz, hw};
                hp.x = *(uint32_t*)&p0; hp.y = *(uint32_t*)&p1;
            }
            lp.x = pack_bf16x2(v.x - __bfloat162float(hx), v.y - __bfloat162float(hy));
            lp.y = pack_bf16x2(v.z - __bfloat162float(hz), v.w - __bfloat162float(hw));
            *(uint2*)(Ahi + row * STRIDE_AB + q * 4) = hp;
            *(uint2*)(Alo + row * STRIDE_AB + q * 4) = lp;
        }
    }

    // ---- Copy pre-split B (hi+lo, 18432B = 1152 uint4) from global (L2-hot) ----
    {
        const uint4* src = (const uint4*)g_B;
        uint4* dst = (uint4*)Bsm;
#pragma unroll
        for (int i = t; i < 1152; i += 128) dst[i] = src[i];
    }

    // ---- Trig: 4 positions x 32 freqs = 128 entries, one per thread ----
    {
        const int ls = t >> 5, n = t & 31;
        const int pos = (bid * 4 + ls) & (NSEQ - 1);
        float sv, cv;
        sincosf((float)pos * inv_freq[n], &sv, &cv);
        SSm[ls][n] = sv;
        CSm[ls][n] = cv;
    }
    __syncthreads();

    // ---- GEMM: warp owns rows [wid*16, wid*16+16), all 64 cols ----
    float acc[8][4];
#pragma unroll
    for (int n = 0; n < 8; n++)
#pragma unroll
        for (int u = 0; u < 4; u++) acc[n][u] = 0.0f;

    // ldmatrix lane roles: matrix m = lane>>3, row rr = lane&7
    const int m  = lane >> 3;
    const int rr = lane & 7;
    // A x4: m0 rows wrow0..+7 k-lo | m1 rows +8..15 k-lo | m2 rows ..7 k-hi | m3 rows 8..15 k-hi
    const uint32_t a_off = (uint32_t)((wid * 16 + ((m & 1) << 3) + rr) * STRIDE_AB) * 2
                         + (uint32_t)((m >> 1) << 4);
    const uint32_t ahi_base = smem_u32(Ahi) + a_off;
    const uint32_t alo_base = smem_u32(Alo) + a_off;
    // B x4 (two n-tiles): m0 rows np*8.. k-lo | m1 same k-hi | m2 rows (np+1)*8.. k-lo | m3 k-hi
    const uint32_t b_off = (uint32_t)(rr * STRIDE_AB) * 2 + (uint32_t)((m & 1) << 4)
                         + (uint32_t)((m >> 1) * 8 * STRIDE_AB * 2);
    const uint32_t bhi_base = smem_u32(Bsm[0]) + b_off;
    const uint32_t blo_base = smem_u32(Bsm[1]) + b_off;

#pragma unroll
    for (int ks = 0; ks < 4; ks++) {
        uint32_t ah0, ah1, ah2, ah3, al0, al1, al2, al3;
        ldsm_x4(ahi_base + ks * 32, ah0, ah1, ah2, ah3);
        ldsm_x4(alo_base + ks * 32, al0, al1, al2, al3);
#pragma unroll
        for (int np = 0; np < 4; np++) {   // n-tile pair (2*np, 2*np+1)
            const uint32_t boff = (uint32_t)(np * 16 * STRIDE_AB * 2) + ks * 32;
            uint32_t bh0, bh1, bh2, bh3, bl0, bl1, bl2, bl3;
            ldsm_x4(bhi_base + boff, bh0, bh1, bh2, bh3);
            ldsm_x4(blo_base + boff, bl0, bl1, bl2, bl3);
            mma16816(acc[2 * np],     ah0, ah1, ah2, ah3, bh0, bh1);
            mma16816(acc[2 * np],     ah0, ah1, ah2, ah3, bl0, bl1);
            mma16816(acc[2 * np],     al0, al1, al2, al3, bh0, bh1);
            mma16816(acc[2 * np + 1], ah0, ah1, ah2, ah3, bh2, bh3);
            mma16816(acc[2 * np + 1], ah0, ah1, ah2, ah3, bl2, bl3);
            mma16816(acc[2 * np + 1], al0, al1, al2, al3, bh2, bh3);
        }
    }
    __syncthreads();  // A reads done; staging overlays A

    // ---- RoPE in registers -> padded staging ----
    // D frag: {c0,c1} = row (wid*16+r), cols (2p,2p+1); {c2,c3} = row+8. p = nt*4+c.
    {
        float* STG = (float*)bufA;
        const int row0 = wid * 16 + r;
#pragma unroll
        for (int nt = 0; nt < 8; nt++) {
            const int p  = nt * 4 + c;
            const float cs = CSm[wid][p];
            const float sn = SSm[wid][p];
            STG[row0 * STRIDE_ST + p]            = (acc[nt][0] * cs - acc[nt][1] * sn) * 32.0f;
            STG[row0 * STRIDE_ST + p + 32]       = (acc[nt][0] * sn + acc[nt][1] * cs) * 32.0f;
            STG[(row0 + 8) * STRIDE_ST + p]      = (acc[nt][2] * cs - acc[nt][3] * sn) * 32.0f;
            STG[(row0 + 8) * STRIDE_ST + p + 32] = (acc[nt][2] * sn + acc[nt][3] * cs) * 32.0f;
        }
    }
    __syncthreads();

    // ---- Coalesced float4 store ----
    {
        const float* STG = (const float*)bufA;
        float4* og = (float4*)out + (long long)bid * 1024;
#pragma unroll
        for (int it = 0; it < 8; it++) {
            const int f   = it * 128 + t;
            const int row = f >> 4;
            const int c4  = f & 15;
            og[f] = *(const float4*)(STG + row * STRIDE_ST + c4 * 4);
        }
    }
}

// ---------------------------------------------------------------------------
// kernel_launch: 0:x 1:thetas 2:theta_scale 3:r_matrix 4:inv_freq 5:pairs
// ---------------------------------------------------------------------------
extern "C" void kernel_launch(void* const* d_in, const int* in_sizes, int n_in,
                              void* d_out, int out_size) {
    const float* x        = (const float*)d_in[0];
    const float* thetas   = (const float*)d_in[1];
    const float* tscale   = (const float*)d_in[2];
    const float* R        = (const float*)d_in[3];
    const float* inv_freq = (const float*)d_in[4];
    const int*   pairs    = (const int*)d_in[5];
    float* out = (float*)d_out;

    build_M_kernel<<<1, 64>>>(thetas, tscale, R, pairs);
    rotary_mma_kernel<<<NCTAS, 128>>>(x, inv_freq, out);
}